// round 16
// baseline (speedup 1.0000x reference)
#include <cuda_runtime.h>
#include <cuda_fp16.h>
#include <stdint.h>

// ---------------------------------------------------------------------------
// Pure fp16 GEMMs (fp32 accum) on mma.sync. R16 = R15's GEMM kernels exactly
// (CTA 128x128, 256 thr, 2 CTAs/SM, Kc=64 two 32-col sub-blocks, 3-stage
// cp.async, one barrier/chunk, hardware tanh.approx GELU), with prep split:
//   prepA (X convert + W1 transpose)  -> critical path for GEMM1
//   prepB (W2 + We transposes)        -> second stream, overlapped with GEMM1
// GEMM2 joins on both. Launched work is identical on every call.
// ---------------------------------------------------------------------------

#define STAGE_BYTES 32768          // A[2][128][64B] 16K | B[2][128][64B] 16K
#define NSTAGES 3
#define SMEM_TOTAL (NSTAGES * STAGE_BYTES)   // 96 KB -> 2 CTAs/SM

// ---------------- static device scratch (no allocations allowed) -----------
static __device__ __align__(16) __half g_Xh [(size_t)32768 * 768];
static __device__ __align__(16) __half g_W1t[(size_t)3072 * 768];     // [N][K]
static __device__ __align__(16) __half g_W2t[(size_t)576 * 3072];     // [N][K]
static __device__ __align__(16) __half g_Wet[(size_t)6 * 192 * 3072];
static __device__ __align__(16) __half g_Hf [(size_t)32768 * 3072];

// ---------------- PTX helpers ----------------------------------------------
__device__ __forceinline__ uint32_t smem_u32(const void* p) {
    uint32_t a;
    asm("{ .reg .u64 t; cvta.to.shared.u64 t, %1; cvt.u32.u64 %0, t; }" : "=r"(a) : "l"(p));
    return a;
}
__device__ __forceinline__ void cp16(uint32_t saddr, const void* g) {
    asm volatile("cp.async.cg.shared.global [%0], [%1], 16;" :: "r"(saddr), "l"(g));
}
#define CP_COMMIT() asm volatile("cp.async.commit_group;" ::: "memory")
#define CP_WAIT(n)  asm volatile("cp.async.wait_group " #n ";" ::: "memory")

__device__ __forceinline__ void ldsm4(uint32_t* r, uint32_t addr) {
    asm volatile("ldmatrix.sync.aligned.m8n8.x4.shared.b16 {%0,%1,%2,%3}, [%4];"
        : "=r"(r[0]), "=r"(r[1]), "=r"(r[2]), "=r"(r[3]) : "r"(addr));
}
__device__ __forceinline__ void mma_f16(float* c, const uint32_t* a,
                                        uint32_t b0, uint32_t b1) {
    asm volatile("mma.sync.aligned.m16n8k16.row.col.f32.f16.f16.f32 "
        "{%0,%1,%2,%3}, {%4,%5,%6,%7}, {%8,%9}, {%0,%1,%2,%3};"
        : "+f"(c[0]), "+f"(c[1]), "+f"(c[2]), "+f"(c[3])
        : "r"(a[0]), "r"(a[1]), "r"(a[2]), "r"(a[3]), "r"(b0), "r"(b1));
}

// gelu via hardware tanh.approx.f32 (single MUFU op)
__device__ __forceinline__ float gelu_fast(float x) {
    float u = 0.7978845608028654f * x * fmaf(0.044715f * x, x, 1.0f);
    float t;
    asm("tanh.approx.f32 %0, %1;" : "=f"(t) : "f"(u));
    return 0.5f * x * (1.0f + t);
}
// int64-vs-int32 robust expert index (values in [0,6) -> int64 odd words all 0)
__device__ __forceinline__ int load_expert_index(const int* __restrict__ idx32, int b) {
    int odd_or = 0;
    #pragma unroll
    for (int j = 1; j < 32; j += 2) odd_or |= idx32[j];
    return (odd_or == 0) ? idx32[2 * b] : idx32[b];
}

// ---------------------------------------------------------------------------
// prepA: X fp32->fp16 (blocks [0,24576)) + W1 transpose (blocks [24576,+2304))
// ---------------------------------------------------------------------------
__global__ void k_prepA(const float* __restrict__ X, const float* __restrict__ W1)
{
    const int b = blockIdx.x;
    const int tid = threadIdx.x;
    if (b < 24576) {
        size_t i = ((size_t)b * 256 + tid) * 4;
        float4 v = *(const float4*)(X + i);
        __half2 a = __floats2half2_rn(v.x, v.y);
        __half2 c = __floats2half2_rn(v.z, v.w);
        uint2 o;
        o.x = *reinterpret_cast<uint32_t*>(&a);
        o.y = *reinterpret_cast<uint32_t*>(&c);
        *(uint2*)(g_Xh + i) = o;
        return;
    }
    int t = b - 24576;                 // W1: R=768, C=3072
    int bx = t % 96, by = t / 96;
    __shared__ float tsh[32][33];
    int tx = tid & 31, ty = tid >> 5;  // (32, 8)
    int bx32 = bx * 32, by32 = by * 32;
    #pragma unroll
    for (int i = 0; i < 32; i += 8)
        tsh[ty + i][tx] = W1[(size_t)(by32 + ty + i) * 3072 + bx32 + tx];
    __syncthreads();
    #pragma unroll
    for (int i = 0; i < 32; i += 8)
        g_W1t[(size_t)(bx32 + ty + i) * 768 + (by32 + tx)] =
            __float2half_rn(tsh[tx][ty + i]);
}

// ---------------------------------------------------------------------------
// prepB: W2 transpose (blocks [0,1728)) + We transpose (blocks [1728,+3456))
// ---------------------------------------------------------------------------
__global__ void k_prepB(const float* __restrict__ W2, const float* __restrict__ We)
{
    const int b = blockIdx.x;
    const int tid = threadIdx.x;
    const float* src; __half* dst; int C, R, bx, by;
    if (b < 1728) {                    // W2: R=3072, C=576
        src = W2; dst = g_W2t; R = 3072; C = 576;
        bx = b % 18; by = b / 18;
    } else {                           // We: 6 x (R=3072, C=192)
        int t = b - 1728;
        int z = t / 576, r = t % 576;
        src = We + (size_t)z * 3072 * 192;
        dst = g_Wet + (size_t)z * 192 * 3072;
        R = 3072; C = 192; bx = r % 6; by = r / 6;
    }
    __shared__ float tsh[32][33];
    int tx = tid & 31, ty = tid >> 5;  // (32, 8)
    int bx32 = bx * 32, by32 = by * 32;
    #pragma unroll
    for (int i = 0; i < 32; i += 8)
        tsh[ty + i][tx] = src[(size_t)(by32 + ty + i) * C + bx32 + tx];
    __syncthreads();
    #pragma unroll
    for (int i = 0; i < 32; i += 8)
        dst[(size_t)(bx32 + ty + i) * R + (by32 + tx)] =
            __float2half_rn(tsh[tx][ty + i]);
}

// ---------------------------------------------------------------------------
// Mainloop compute: chunk = 64 K-columns as two 32-col sub-blocks.
// Stage layout: A sub0 +0, A sub1 +8192, B sub0 +16384, B sub1 +24576.
// Each sub-block: 128 rows x 64 B, 16B-chunk swizzle p = ch ^ ((r>>1)&3).
// ---------------------------------------------------------------------------

struct Frags {
    float acc[2][8][4];
};

__device__ __forceinline__ void compute_chunk(uint32_t base, int st, int lane,
                                              int wm, int wn, Frags& F)
{
    const uint32_t Ab = base + st;
    const uint32_t Bb = base + st + 16384;
    const int m8 = lane >> 3, l7 = lane & 7;
    #pragma unroll
    for (int ks = 0; ks < 4; ks++) {
        const uint32_t Asub = Ab + (ks >> 1) * 8192;
        const uint32_t Bsub = Bb + (ks >> 1) * 8192;
        const int kk = ks & 1;
        uint32_t a[2][4];
        #pragma unroll
        for (int mi = 0; mi < 2; mi++) {
            int rr = wm * 32 + mi * 16 + (m8 & 1) * 8 + l7;
            int ch = kk * 2 + (m8 >> 1);
            int p = ch ^ ((rr >> 1) & 3);
            ldsm4(a[mi], Asub + (uint32_t)(rr * 64 + p * 16));
        }
        #pragma unroll
        for (int jp = 0; jp < 4; jp++) {
            int nrow = wn * 64 + jp * 16 + (m8 >> 1) * 8 + l7;
            int ch = kk * 2 + (m8 & 1);
            int p = ch ^ ((nrow >> 1) & 3);
            uint32_t tb[4];
            ldsm4(tb, Bsub + (uint32_t)(nrow * 64 + p * 16));
            #pragma unroll
            for (int mi = 0; mi < 2; mi++) {
                mma_f16(F.acc[mi][2 * jp],     a[mi], tb[0], tb[1]);
                mma_f16(F.acc[mi][2 * jp + 1], a[mi], tb[2], tb[3]);
            }
        }
    }
}

// ---------------------------------------------------------------------------
// GEMM1: H = gelu(X @ W1 + b1).  A = Xh [32768][768], B = W1t [3072][768]
// Grid (24, 256), 256 threads, 2 CTAs/SM.  NC = 768/64 = 12.
// ---------------------------------------------------------------------------
__global__ void __launch_bounds__(256, 2)
k_mm1(const float* __restrict__ b1)
{
    extern __shared__ char smem[];
    const uint32_t base = smem_u32(smem);
    const int tid = threadIdx.x, wid = tid >> 5, lane = tid & 31;
    const int bx = blockIdx.x, by = blockIdx.y;
    const int K = 768, NC = 12;
    const int wm = wid & 3, wn = wid >> 2;

    auto issue = [&](int c) {
        int st = (c % NSTAGES) * STAGE_BYTES;
        #pragma unroll
        for (int t = 0; t < 8; t++) {
            int idx = tid + t * 256;           // 0..2047
            int region = idx >> 9;             // 0: A0, 1: A1, 2: B0, 3: B1
            int w = idx & 511, r = w >> 2, ch = w & 3;
            int sub = region & 1;
            int isB = region >> 1;
            int p = ch ^ ((r >> 1) & 3);
            uint32_t sa = base + st + isB * 16384 + sub * 8192 + r * 64 + p * 16;
            const __half* src;
            size_t grow;
            if (!isB) { src = g_Xh;  grow = (size_t)(by * 128 + r) * K; }
            else      { src = g_W1t; grow = (size_t)(bx * 128 + r) * K; }
            cp16(sa, src + grow + c * 64 + sub * 32 + ch * 8);
        }
        CP_COMMIT();
    };

    Frags F;
    #pragma unroll
    for (int mi = 0; mi < 2; mi++)
        #pragma unroll
        for (int nj = 0; nj < 8; nj++)
            #pragma unroll
            for (int q = 0; q < 4; q++) F.acc[mi][nj][q] = 0.0f;

    issue(0); issue(1);
    for (int c = 0; c < NC; c++) {
        CP_WAIT(1);
        __syncthreads();
        if (c + 2 < NC) issue(c + 2); else CP_COMMIT();
        compute_chunk(base, (c % NSTAGES) * STAGE_BYTES, lane, wm, wn, F);
    }

    // epilogue: bias + fast GELU -> fp16 into H
    const int g = lane >> 2, t4 = lane & 3;
    #pragma unroll
    for (int mi = 0; mi < 2; mi++) {
        #pragma unroll
        for (int nj = 0; nj < 8; nj++) {
            int row0 = by * 128 + wm * 32 + mi * 16 + g;
            int col  = bx * 128 + wn * 64 + nj * 8 + 2 * t4;
            float2 bb = *(const float2*)(b1 + col);
            float x0 = gelu_fast(F.acc[mi][nj][0] + bb.x);
            float x1 = gelu_fast(F.acc[mi][nj][1] + bb.y);
            float x2 = gelu_fast(F.acc[mi][nj][2] + bb.x);
            float x3 = gelu_fast(F.acc[mi][nj][3] + bb.y);
            __half2 h01 = __floats2half2_rn(x0, x1);
            __half2 h23 = __floats2half2_rn(x2, x3);
            *(uint32_t*)(g_Hf + (size_t)row0 * 3072 + col) =
                *reinterpret_cast<uint32_t*>(&h01);
            *(uint32_t*)(g_Hf + (size_t)(row0 + 8) * 3072 + col) =
                *reinterpret_cast<uint32_t*>(&h23);
        }
    }
}

// ---------------------------------------------------------------------------
// GEMM2: out = H @ [W2 | We[idx]] + [b2 | be[idx]].  Grid (6, 256), 2 CTAs/SM.
// NC = 3072/64 = 48. B rows n<576 from W2t, n>=576 from Wet[e]; 128-row M
// tiles never straddle a batch (1024 rows / batch).
// ---------------------------------------------------------------------------
__global__ void __launch_bounds__(256, 2)
k_mm2(const float* __restrict__ b2, const float* __restrict__ be,
      const int* __restrict__ idx32, float* __restrict__ out)
{
    extern __shared__ char smem[];
    const uint32_t base = smem_u32(smem);
    const int tid = threadIdx.x, wid = tid >> 5, lane = tid & 31;
    const int bx = blockIdx.x, by = blockIdx.y;
    const int K = 3072, NC = 48;
    const int wm = wid & 3, wn = wid >> 2;
    const int e = load_expert_index(idx32, by >> 3);

    auto issue = [&](int c) {
        int st = (c % NSTAGES) * STAGE_BYTES;
        #pragma unroll
        for (int t = 0; t < 8; t++) {
            int idx = tid + t * 256;
            int region = idx >> 9;
            int w = idx & 511, r = w >> 2, ch = w & 3;
            int sub = region & 1;
            int isB = region >> 1;
            int p = ch ^ ((r >> 1) & 3);
            uint32_t sa = base + st + isB * 16384 + sub * 8192 + r * 64 + p * 16;
            const __half* src;
            size_t grow;
            if (!isB) {
                src = g_Hf;
                grow = (size_t)(by * 128 + r) * K;
            } else {
                int n = bx * 128 + r;
                if (n < 576) { src = g_W2t; grow = (size_t)n * K; }
                else { src = g_Wet; grow = ((size_t)e * 192 + (n - 576)) * K; }
            }
            cp16(sa, src + grow + c * 64 + sub * 32 + ch * 8);
        }
        CP_COMMIT();
    };

    Frags F;
    #pragma unroll
    for (int mi = 0; mi < 2; mi++)
        #pragma unroll
        for (int nj = 0; nj < 8; nj++)
            #pragma unroll
            for (int q = 0; q < 4; q++) F.acc[mi][nj][q] = 0.0f;

    issue(0); issue(1);
    for (int c = 0; c < NC; c++) {
        CP_WAIT(1);
        __syncthreads();
        if (c + 2 < NC) issue(c + 2); else CP_COMMIT();
        compute_chunk(base, (c % NSTAGES) * STAGE_BYTES, lane, wm, wn, F);
    }

    // epilogue: + bias (shared / expert), fp32 out [32768][768]
    const int g = lane >> 2, t4 = lane & 3;
    #pragma unroll
    for (int mi = 0; mi < 2; mi++) {
        #pragma unroll
        for (int nj = 0; nj < 8; nj++) {
            int row0 = by * 128 + wm * 32 + mi * 16 + g;
            int col  = bx * 128 + wn * 64 + nj * 8 + 2 * t4;
            float bx0, bx1;
            if (col < 576) { float2 bb = *(const float2*)(b2 + col); bx0 = bb.x; bx1 = bb.y; }
            else { float2 bb = *(const float2*)(be + e * 192 + (col - 576)); bx0 = bb.x; bx1 = bb.y; }
            float2 v0 = make_float2(F.acc[mi][nj][0] + bx0, F.acc[mi][nj][1] + bx1);
            float2 v1 = make_float2(F.acc[mi][nj][2] + bx0, F.acc[mi][nj][3] + bx1);
            *(float2*)(out + (size_t)row0 * 768 + col) = v0;
            *(float2*)(out + (size_t)(row0 + 8) * 768 + col) = v1;
        }
    }
}

// ---------------------------------------------------------------------------
extern "C" void kernel_launch(void* const* d_in, const int* in_sizes, int n_in,
                              void* d_out, int out_size)
{
    (void)in_sizes; (void)n_in; (void)out_size;
    const float* X   = (const float*)d_in[0];
    const int*   idx = (const int*)d_in[1];
    const float* W1  = (const float*)d_in[2];
    const float* b1  = (const float*)d_in[3];
    const float* W2  = (const float*)d_in[4];
    const float* b2  = (const float*)d_in[5];
    const float* We  = (const float*)d_in[6];
    const float* be  = (const float*)d_in[7];
    float* out = (float*)d_out;

    cudaFuncSetAttribute(k_mm1, cudaFuncAttributeMaxDynamicSharedMemorySize, SMEM_TOTAL);
    cudaFuncSetAttribute(k_mm2, cudaFuncAttributeMaxDynamicSharedMemorySize, SMEM_TOTAL);

    // One-time handles (identical launched work on every call; no device allocs).
    static cudaStream_t s2 = nullptr;
    static cudaEvent_t evFork = nullptr, evJoin = nullptr;
    if (!s2) {
        cudaStreamCreateWithFlags(&s2, cudaStreamNonBlocking);
        cudaEventCreateWithFlags(&evFork, cudaEventDisableTiming);
        cudaEventCreateWithFlags(&evJoin, cudaEventDisableTiming);
    }

    // Fork: prepB (W2/We, needed only by GEMM2) runs on s2, overlapped with
    // prepA + GEMM1 on the main stream. GEMM2 joins on both.
    cudaEventRecord(evFork, 0);
    cudaStreamWaitEvent(s2, evFork, 0);
    k_prepB<<<1728 + 3456, 256, 0, s2>>>(W2, We);
    cudaEventRecord(evJoin, s2);

    k_prepA<<<24576 + 2304, 256>>>(X, W1);
    k_mm1<<<dim3(3072 / 128, 32768 / 128), 256, SMEM_TOTAL>>>(b1);

    cudaStreamWaitEvent(0, evJoin, 0);
    k_mm2<<<dim3(768 / 128, 32768 / 128), 256, SMEM_TOTAL>>>(b2, be, idx, out);
}

// round 17
// speedup vs baseline: 1.5484x; 1.5484x over previous
#include <cuda_runtime.h>
#include <cuda_fp16.h>
#include <stdint.h>

// ---------------------------------------------------------------------------
// Pure fp16 GEMMs (fp32 accum) on mma.sync. R17 = exact R15 (best: serial
// 3-node graph — prep -> mm1 -> mm2; CTA 128x128, 256 thr, 2 CTAs/SM, Kc=64
// two 32-col sub-blocks, 3-stage cp.async, one barrier/chunk, hardware
// tanh.approx GELU). R16's dual-stream fork reverted (it slowed BOTH GEMMs
// ~20% at the graph level). Only change: X-convert region of k_prep does
// 8 elems/thread (12288 blocks instead of 24576; identical numerics).
// ---------------------------------------------------------------------------

#define STAGE_BYTES 32768          // A[2][128][64B] 16K | B[2][128][64B] 16K
#define NSTAGES 3
#define SMEM_TOTAL (NSTAGES * STAGE_BYTES)   // 96 KB -> 2 CTAs/SM

// ---------------- static device scratch (no allocations allowed) -----------
static __device__ __align__(16) __half g_Xh [(size_t)32768 * 768];
static __device__ __align__(16) __half g_W1t[(size_t)3072 * 768];     // [N][K]
static __device__ __align__(16) __half g_W2t[(size_t)576 * 3072];     // [N][K]
static __device__ __align__(16) __half g_Wet[(size_t)6 * 192 * 3072];
static __device__ __align__(16) __half g_Hf [(size_t)32768 * 3072];

// ---------------- PTX helpers ----------------------------------------------
__device__ __forceinline__ uint32_t smem_u32(const void* p) {
    uint32_t a;
    asm("{ .reg .u64 t; cvta.to.shared.u64 t, %1; cvt.u32.u64 %0, t; }" : "=r"(a) : "l"(p));
    return a;
}
__device__ __forceinline__ void cp16(uint32_t saddr, const void* g) {
    asm volatile("cp.async.cg.shared.global [%0], [%1], 16;" :: "r"(saddr), "l"(g));
}
#define CP_COMMIT() asm volatile("cp.async.commit_group;" ::: "memory")
#define CP_WAIT(n)  asm volatile("cp.async.wait_group " #n ";" ::: "memory")

__device__ __forceinline__ void ldsm4(uint32_t* r, uint32_t addr) {
    asm volatile("ldmatrix.sync.aligned.m8n8.x4.shared.b16 {%0,%1,%2,%3}, [%4];"
        : "=r"(r[0]), "=r"(r[1]), "=r"(r[2]), "=r"(r[3]) : "r"(addr));
}
__device__ __forceinline__ void mma_f16(float* c, const uint32_t* a,
                                        uint32_t b0, uint32_t b1) {
    asm volatile("mma.sync.aligned.m16n8k16.row.col.f32.f16.f16.f32 "
        "{%0,%1,%2,%3}, {%4,%5,%6,%7}, {%8,%9}, {%0,%1,%2,%3};"
        : "+f"(c[0]), "+f"(c[1]), "+f"(c[2]), "+f"(c[3])
        : "r"(a[0]), "r"(a[1]), "r"(a[2]), "r"(a[3]), "r"(b0), "r"(b1));
}

// gelu via hardware tanh.approx.f32 (single MUFU op)
__device__ __forceinline__ float gelu_fast(float x) {
    float u = 0.7978845608028654f * x * fmaf(0.044715f * x, x, 1.0f);
    float t;
    asm("tanh.approx.f32 %0, %1;" : "=f"(t) : "f"(u));
    return 0.5f * x * (1.0f + t);
}
// int64-vs-int32 robust expert index (values in [0,6) -> int64 odd words all 0)
__device__ __forceinline__ int load_expert_index(const int* __restrict__ idx32, int b) {
    int odd_or = 0;
    #pragma unroll
    for (int j = 1; j < 32; j += 2) odd_or |= idx32[j];
    return (odd_or == 0) ? idx32[2 * b] : idx32[b];
}

// ---------------------------------------------------------------------------
// Fused prep: one launch. Region-decoded 1D grid of 256-thread blocks.
//  [0, 12288)     : X fp32 -> fp16 (8 elems/thread)
//  [12288, +2304) : W1 transpose (R=768,  C=3072)
//  [.., +1728)    : W2 transpose (R=3072, C=576)
//  [.., +3456)    : We transpose (R=3072, C=192, 6 experts)
// ---------------------------------------------------------------------------
__global__ void k_prep(const float* __restrict__ X, const float* __restrict__ W1,
                       const float* __restrict__ W2, const float* __restrict__ We)
{
    const int b = blockIdx.x;
    const int tid = threadIdx.x;
    if (b < 12288) {
        size_t i = ((size_t)b * 256 + tid) * 8;
        float4 v0 = *(const float4*)(X + i);
        float4 v1 = *(const float4*)(X + i + 4);
        __half2 a0 = __floats2half2_rn(v0.x, v0.y);
        __half2 a1 = __floats2half2_rn(v0.z, v0.w);
        __half2 a2 = __floats2half2_rn(v1.x, v1.y);
        __half2 a3 = __floats2half2_rn(v1.z, v1.w);
        uint4 o;
        o.x = *reinterpret_cast<uint32_t*>(&a0);
        o.y = *reinterpret_cast<uint32_t*>(&a1);
        o.z = *reinterpret_cast<uint32_t*>(&a2);
        o.w = *reinterpret_cast<uint32_t*>(&a3);
        *(uint4*)(g_Xh + i) = o;
        return;
    }
    const float* src; __half* dst; int R, C, bx, by;
    int t = b - 12288;
    if (t < 2304)                { src = W1; dst = g_W1t; R = 768;  C = 3072; bx = t % 96; by = t / 96; }
    else if ((t -= 2304) < 1728) { src = W2; dst = g_W2t; R = 3072; C = 576;  bx = t % 18; by = t / 18; }
    else {
        t -= 1728;
        int z = t / 576, r = t % 576;
        src = We + (size_t)z * 3072 * 192;
        dst = g_Wet + (size_t)z * 192 * 3072;
        R = 3072; C = 192; bx = r % 6; by = r / 6;
    }
    __shared__ float tsh[32][33];
    int tx = tid & 31, ty = tid >> 5;  // (32, 8)
    int bx32 = bx * 32, by32 = by * 32;
    #pragma unroll
    for (int i = 0; i < 32; i += 8)
        tsh[ty + i][tx] = src[(size_t)(by32 + ty + i) * C + bx32 + tx];
    __syncthreads();
    #pragma unroll
    for (int i = 0; i < 32; i += 8)
        dst[(size_t)(bx32 + ty + i) * R + (by32 + tx)] = __float2half_rn(tsh[tx][ty + i]);
}

// ---------------------------------------------------------------------------
// Mainloop compute: chunk = 64 K-columns as two 32-col sub-blocks.
// Stage layout: A sub0 +0, A sub1 +8192, B sub0 +16384, B sub1 +24576.
// Each sub-block: 128 rows x 64 B, 16B-chunk swizzle p = ch ^ ((r>>1)&3).
// ---------------------------------------------------------------------------

struct Frags {
    float acc[2][8][4];
};

__device__ __forceinline__ void compute_chunk(uint32_t base, int st, int lane,
                                              int wm, int wn, Frags& F)
{
    const uint32_t Ab = base + st;
    const uint32_t Bb = base + st + 16384;
    const int m8 = lane >> 3, l7 = lane & 7;
    #pragma unroll
    for (int ks = 0; ks < 4; ks++) {
        const uint32_t Asub = Ab + (ks >> 1) * 8192;
        const uint32_t Bsub = Bb + (ks >> 1) * 8192;
        const int kk = ks & 1;
        uint32_t a[2][4];
        #pragma unroll
        for (int mi = 0; mi < 2; mi++) {
            int rr = wm * 32 + mi * 16 + (m8 & 1) * 8 + l7;
            int ch = kk * 2 + (m8 >> 1);
            int p = ch ^ ((rr >> 1) & 3);
            ldsm4(a[mi], Asub + (uint32_t)(rr * 64 + p * 16));
        }
        #pragma unroll
        for (int jp = 0; jp < 4; jp++) {
            int nrow = wn * 64 + jp * 16 + (m8 >> 1) * 8 + l7;
            int ch = kk * 2 + (m8 & 1);
            int p = ch ^ ((nrow >> 1) & 3);
            uint32_t tb[4];
            ldsm4(tb, Bsub + (uint32_t)(nrow * 64 + p * 16));
            #pragma unroll
            for (int mi = 0; mi < 2; mi++) {
                mma_f16(F.acc[mi][2 * jp],     a[mi], tb[0], tb[1]);
                mma_f16(F.acc[mi][2 * jp + 1], a[mi], tb[2], tb[3]);
            }
        }
    }
}

// ---------------------------------------------------------------------------
// GEMM1: H = gelu(X @ W1 + b1).  A = Xh [32768][768], B = W1t [3072][768]
// Grid (24, 256), 256 threads, 2 CTAs/SM.  NC = 768/64 = 12.
// ---------------------------------------------------------------------------
__global__ void __launch_bounds__(256, 2)
k_mm1(const float* __restrict__ b1)
{
    extern __shared__ char smem[];
    const uint32_t base = smem_u32(smem);
    const int tid = threadIdx.x, wid = tid >> 5, lane = tid & 31;
    const int bx = blockIdx.x, by = blockIdx.y;
    const int K = 768, NC = 12;
    const int wm = wid & 3, wn = wid >> 2;

    auto issue = [&](int c) {
        int st = (c % NSTAGES) * STAGE_BYTES;
        #pragma unroll
        for (int t = 0; t < 8; t++) {
            int idx = tid + t * 256;           // 0..2047
            int region = idx >> 9;             // 0: A0, 1: A1, 2: B0, 3: B1
            int w = idx & 511, r = w >> 2, ch = w & 3;
            int sub = region & 1;
            int isB = region >> 1;
            int p = ch ^ ((r >> 1) & 3);
            uint32_t sa = base + st + isB * 16384 + sub * 8192 + r * 64 + p * 16;
            const __half* src;
            size_t grow;
            if (!isB) { src = g_Xh;  grow = (size_t)(by * 128 + r) * K; }
            else      { src = g_W1t; grow = (size_t)(bx * 128 + r) * K; }
            cp16(sa, src + grow + c * 64 + sub * 32 + ch * 8);
        }
        CP_COMMIT();
    };

    Frags F;
    #pragma unroll
    for (int mi = 0; mi < 2; mi++)
        #pragma unroll
        for (int nj = 0; nj < 8; nj++)
            #pragma unroll
            for (int q = 0; q < 4; q++) F.acc[mi][nj][q] = 0.0f;

    issue(0); issue(1);
    for (int c = 0; c < NC; c++) {
        CP_WAIT(1);
        __syncthreads();
        if (c + 2 < NC) issue(c + 2); else CP_COMMIT();
        compute_chunk(base, (c % NSTAGES) * STAGE_BYTES, lane, wm, wn, F);
    }

    // epilogue: bias + fast GELU -> fp16 into H
    const int g = lane >> 2, t4 = lane & 3;
    #pragma unroll
    for (int mi = 0; mi < 2; mi++) {
        #pragma unroll
        for (int nj = 0; nj < 8; nj++) {
            int row0 = by * 128 + wm * 32 + mi * 16 + g;
            int col  = bx * 128 + wn * 64 + nj * 8 + 2 * t4;
            float2 bb = *(const float2*)(b1 + col);
            float x0 = gelu_fast(F.acc[mi][nj][0] + bb.x);
            float x1 = gelu_fast(F.acc[mi][nj][1] + bb.y);
            float x2 = gelu_fast(F.acc[mi][nj][2] + bb.x);
            float x3 = gelu_fast(F.acc[mi][nj][3] + bb.y);
            __half2 h01 = __floats2half2_rn(x0, x1);
            __half2 h23 = __floats2half2_rn(x2, x3);
            *(uint32_t*)(g_Hf + (size_t)row0 * 3072 + col) =
                *reinterpret_cast<uint32_t*>(&h01);
            *(uint32_t*)(g_Hf + (size_t)(row0 + 8) * 3072 + col) =
                *reinterpret_cast<uint32_t*>(&h23);
        }
    }
}

// ---------------------------------------------------------------------------
// GEMM2: out = H @ [W2 | We[idx]] + [b2 | be[idx]].  Grid (6, 256), 2 CTAs/SM.
// NC = 3072/64 = 48. B rows n<576 from W2t, n>=576 from Wet[e]; 128-row M
// tiles never straddle a batch (1024 rows / batch).
// ---------------------------------------------------------------------------
__global__ void __launch_bounds__(256, 2)
k_mm2(const float* __restrict__ b2, const float* __restrict__ be,
      const int* __restrict__ idx32, float* __restrict__ out)
{
    extern __shared__ char smem[];
    const uint32_t base = smem_u32(smem);
    const int tid = threadIdx.x, wid = tid >> 5, lane = tid & 31;
    const int bx = blockIdx.x, by = blockIdx.y;
    const int K = 3072, NC = 48;
    const int wm = wid & 3, wn = wid >> 2;
    const int e = load_expert_index(idx32, by >> 3);

    auto issue = [&](int c) {
        int st = (c % NSTAGES) * STAGE_BYTES;
        #pragma unroll
        for (int t = 0; t < 8; t++) {
            int idx = tid + t * 256;
            int region = idx >> 9;
            int w = idx & 511, r = w >> 2, ch = w & 3;
            int sub = region & 1;
            int isB = region >> 1;
            int p = ch ^ ((r >> 1) & 3);
            uint32_t sa = base + st + isB * 16384 + sub * 8192 + r * 64 + p * 16;
            const __half* src;
            size_t grow;
            if (!isB) {
                src = g_Hf;
                grow = (size_t)(by * 128 + r) * K;
            } else {
                int n = bx * 128 + r;
                if (n < 576) { src = g_W2t; grow = (size_t)n * K; }
                else { src = g_Wet; grow = ((size_t)e * 192 + (n - 576)) * K; }
            }
            cp16(sa, src + grow + c * 64 + sub * 32 + ch * 8);
        }
        CP_COMMIT();
    };

    Frags F;
    #pragma unroll
    for (int mi = 0; mi < 2; mi++)
        #pragma unroll
        for (int nj = 0; nj < 8; nj++)
            #pragma unroll
            for (int q = 0; q < 4; q++) F.acc[mi][nj][q] = 0.0f;

    issue(0); issue(1);
    for (int c = 0; c < NC; c++) {
        CP_WAIT(1);
        __syncthreads();
        if (c + 2 < NC) issue(c + 2); else CP_COMMIT();
        compute_chunk(base, (c % NSTAGES) * STAGE_BYTES, lane, wm, wn, F);
    }

    // epilogue: + bias (shared / expert), fp32 out [32768][768]
    const int g = lane >> 2, t4 = lane & 3;
    #pragma unroll
    for (int mi = 0; mi < 2; mi++) {
        #pragma unroll
        for (int nj = 0; nj < 8; nj++) {
            int row0 = by * 128 + wm * 32 + mi * 16 + g;
            int col  = bx * 128 + wn * 64 + nj * 8 + 2 * t4;
            float bx0, bx1;
            if (col < 576) { float2 bb = *(const float2*)(b2 + col); bx0 = bb.x; bx1 = bb.y; }
            else { float2 bb = *(const float2*)(be + e * 192 + (col - 576)); bx0 = bb.x; bx1 = bb.y; }
            float2 v0 = make_float2(F.acc[mi][nj][0] + bx0, F.acc[mi][nj][1] + bx1);
            float2 v1 = make_float2(F.acc[mi][nj][2] + bx0, F.acc[mi][nj][3] + bx1);
            *(float2*)(out + (size_t)row0 * 768 + col) = v0;
            *(float2*)(out + (size_t)(row0 + 8) * 768 + col) = v1;
        }
    }
}

// ---------------------------------------------------------------------------
extern "C" void kernel_launch(void* const* d_in, const int* in_sizes, int n_in,
                              void* d_out, int out_size)
{
    (void)in_sizes; (void)n_in; (void)out_size;
    const float* X   = (const float*)d_in[0];
    const int*   idx = (const int*)d_in[1];
    const float* W1  = (const float*)d_in[2];
    const float* b1  = (const float*)d_in[3];
    const float* W2  = (const float*)d_in[4];
    const float* b2  = (const float*)d_in[5];
    const float* We  = (const float*)d_in[6];
    const float* be  = (const float*)d_in[7];
    float* out = (float*)d_out;

    cudaFuncSetAttribute(k_mm1, cudaFuncAttributeMaxDynamicSharedMemorySize, SMEM_TOTAL);
    cudaFuncSetAttribute(k_mm2, cudaFuncAttributeMaxDynamicSharedMemorySize, SMEM_TOTAL);

    // fused prep: X convert + W1/W2/We transposes in one launch (serial graph)
    k_prep<<<12288 + 2304 + 1728 + 3456, 256>>>(X, W1, W2, We);

    k_mm1<<<dim3(3072 / 128, 32768 / 128), 256, SMEM_TOTAL>>>(b1);
    k_mm2<<<dim3(768 / 128, 32768 / 128), 256, SMEM_TOTAL>>>(b2, be, idx, out);
}